// round 6
// baseline (speedup 1.0000x reference)
#include <cuda_runtime.h>
#include <math_constants.h>

// Problem constants
#define Bb 2
#define Hh 16
#define Ss 2048
#define Dd 64

// Tiling
#define TQ 128
#define TK 64
#define NT 256
#define KTILES (Ss / TK)        // 32

// smem strides (floats) — all chosen so fragment LDS are conflict-free:
//   Q/P [q][d] stride 68: lane addr ≡ gid*4 + tig (mod 32)   -> 32 distinct
//   K   [k][d] stride 68, read as B[d][kcol] = kb[kcol*68+d]  -> gid*4+tig
//   V   [k][d] stride 72, read as B[k][n]    = vb[k*72+n]     -> tig*8+gid
#define QSV 68
#define KSK 68
#define TSV 72

// smem layout (floats) — sweep-1 view
#define OFF_Q   0               // 128*68 = 8704
#define OFF_K0  8704            // 64*68  = 4352
#define OFF_K1  13056
// sweep-2 overlay
#define OFF_V0  0               // 64*72 = 4608
#define OFF_V1  4608
#define OFF_P   9216            // 128*68 = 8704
#define SMEM_FLOATS 17920       // 71680 B

// mask dtype flag: 1 -> 4-byte elements, 0 -> 1-byte
__device__ int g_mask_elem4;
// packed mask bits: [B, S, S/32] words
#define MASK_WORDS (Bb * Ss * (Ss / 32))
__device__ unsigned g_maskbits[MASK_WORDS];

__global__ void detect_mask_kernel(const unsigned int* __restrict__ mw)
{
    int has_bigbyte = 0, has_bigword = 0;
    for (int i = threadIdx.x; i < 4096; i += NT) {
        unsigned w = mw[i];
        if ((w & 0xffu) > 1u || ((w >> 8) & 0xffu) > 1u ||
            ((w >> 16) & 0xffu) > 1u || ((w >> 24) & 0xffu) > 1u) has_bigbyte = 1;
        if (w > 1u) has_bigword = 1;
    }
    has_bigbyte = __syncthreads_or(has_bigbyte);
    has_bigword = __syncthreads_or(has_bigword);
    if (threadIdx.x == 0)
        g_mask_elem4 = has_bigbyte ? 1 : (has_bigword ? 0 : 1);
}

__global__ void mask_pack_kernel(const void* __restrict__ mask)
{
    int w = blockIdx.x * blockDim.x + threadIdx.x;
    if (w >= MASK_WORDS) return;
    unsigned bits = 0;
    if (g_mask_elem4) {
        const uint4* p = (const uint4*)mask + (size_t)w * 8;
#pragma unroll
        for (int j = 0; j < 8; j++) {
            uint4 v = p[j];
            bits |= ((unsigned)(v.x != 0u)) << (4 * j);
            bits |= ((unsigned)(v.y != 0u)) << (4 * j + 1);
            bits |= ((unsigned)(v.z != 0u)) << (4 * j + 2);
            bits |= ((unsigned)(v.w != 0u)) << (4 * j + 3);
        }
    } else {
        const uint4* p = (const uint4*)mask + (size_t)w * 2;
#pragma unroll
        for (int j = 0; j < 2; j++) {
            uint4 v = p[j];
            unsigned vv[4] = {v.x, v.y, v.z, v.w};
#pragma unroll
            for (int q = 0; q < 4; q++)
#pragma unroll
                for (int bbit = 0; bbit < 4; bbit++)
                    bits |= ((unsigned)(((vv[q] >> (8 * bbit)) & 0xffu) != 0u))
                            << (16 * j + 4 * q + bbit);
        }
    }
    g_maskbits[w] = bits;
}

__device__ __forceinline__ unsigned f2tf32(float x)
{
    unsigned r;
    asm("cvt.rna.tf32.f32 %0, %1;" : "=r"(r) : "f"(x));
    return r;
}

__device__ __forceinline__ unsigned smem_u32(const void* p)
{
    unsigned r;
    asm("{ .reg .u64 t; cvta.to.shared.u64 t, %1; cvt.u32.u64 %0, t; }"
        : "=r"(r) : "l"(p));
    return r;
}

__device__ __forceinline__ void cpa16(unsigned s, const void* g)
{
    asm volatile("cp.async.cg.shared.global [%0], [%1], 16;" :: "r"(s), "l"(g));
}
#define CPA_COMMIT() asm volatile("cp.async.commit_group;")
#define CPA_WAIT(N)  asm volatile("cp.async.wait_group %0;" :: "n"(N) : "memory")

__device__ __forceinline__ void mma8(float* c,
                                     unsigned a0, unsigned a1, unsigned a2, unsigned a3,
                                     unsigned b0, unsigned b1)
{
    asm volatile(
        "mma.sync.aligned.m16n8k8.row.col.f32.tf32.tf32.f32 "
        "{%0,%1,%2,%3}, {%4,%5,%6,%7}, {%8,%9}, {%0,%1,%2,%3};\n"
        : "+f"(c[0]), "+f"(c[1]), "+f"(c[2]), "+f"(c[3])
        : "r"(a0), "r"(a1), "r"(a2), "r"(a3), "r"(b0), "r"(b1));
}

// split fp32 -> (hi tf32 bits, lo residual bits; HW truncates lo to tf32)
__device__ __forceinline__ void split2(float x, unsigned& hi, unsigned& lo)
{
    hi = f2tf32(x);
    lo = __float_as_uint(x - __uint_as_float(hi));
}

__global__ __launch_bounds__(NT, 2)
void attn_mma_kernel(const float* __restrict__ Qg_,
                     const float* __restrict__ Kg_,
                     const float* __restrict__ Vg_,
                     float* __restrict__ ctx_out,
                     float* __restrict__ att_out)
{
    extern __shared__ float sm[];
    const int tid  = threadIdx.x;
    const int lane = tid & 31;
    const int wid  = tid >> 5;          // 8 warps
    const int gid  = lane >> 2;         // 0..7
    const int tig  = lane & 3;          // 0..3
    const int r0   = wid * 16 + gid;    // local q rows
    const int r1   = r0 + 8;

    const int qt = blockIdx.x;
    const int bh = blockIdx.y;
    const int b  = bh >> 4;
    const int q0 = qt * TQ;

    const size_t head_off = (size_t)bh * Ss * Dd;
    const float* Qg = Qg_ + head_off + (size_t)q0 * Dd;
    const float* Kg = Kg_ + head_off;
    const float* Vg = Vg_ + head_off;
    float* att = att_out + (size_t)bh * Ss * Ss + (size_t)q0 * Ss;
    float* ctx = ctx_out + head_off + (size_t)q0 * Dd;
    const unsigned* mb_r0 = g_maskbits + ((size_t)b * Ss + q0 + r0) * (Ss / 32);
    const unsigned* mb_r1 = g_maskbits + ((size_t)b * Ss + q0 + r1) * (Ss / 32);

    const float scale = 0.125f;     // 1/sqrt(64)
    const float NEG = -1e9f;

    float* q_s = sm + OFF_Q;
    float* kbuf[2] = {sm + OFF_K0, sm + OFF_K1};

    // ---- Prologue: async-copy Q tile + K tile 0 (both natural [row][d]) ----
    {
#pragma unroll
        for (int i = 0; i < 8; i++) {
            int c = tid + i * NT;
            int row = c >> 4, ch = c & 15;
            cpa16(smem_u32(&q_s[row * QSV + ch * 4]), Qg + row * Dd + ch * 4);
        }
#pragma unroll
        for (int i = 0; i < 4; i++) {
            int c = tid + i * NT;
            int row = c >> 4, ch = c & 15;
            cpa16(smem_u32(&kbuf[0][row * KSK + ch * 4]), Kg + row * Dd + ch * 4);
        }
        CPA_COMMIT();
    }

    float m0 = -CUDART_INF_F, m1 = -CUDART_INF_F, l0 = 0.0f, l1 = 0.0f;

    // ================= Sweep 1: raw scores + online (m, l) =================
    for (int kt = 0; kt < KTILES; kt++) {
        const float* kb = kbuf[kt & 1];
        if (kt + 1 < KTILES) {
            float* nb_ = kbuf[(kt + 1) & 1];
            const float* src = Kg + (size_t)(kt + 1) * TK * Dd;
#pragma unroll
            for (int i = 0; i < 4; i++) {
                int c = tid + i * NT;
                int row = c >> 4, ch = c & 15;
                cpa16(smem_u32(&nb_[row * KSK + ch * 4]), src + row * Dd + ch * 4);
            }
            CPA_COMMIT();
            CPA_WAIT(1);
        } else {
            CPA_WAIT(0);
        }
        __syncthreads();

        float acc[8][4];
#pragma unroll
        for (int n = 0; n < 8; n++)
#pragma unroll
            for (int j = 0; j < 4; j++) acc[n][j] = 0.0f;

#pragma unroll
        for (int ksi = 0; ksi < 8; ksi++) {
            const int d0 = ksi * 8 + tig;
            const int d4 = d0 + 4;
            unsigned ah0, ah1, ah2, ah3, al0, al1, al2, al3;
            split2(q_s[r0 * QSV + d0], ah0, al0);
            split2(q_s[r1 * QSV + d0], ah1, al1);
            split2(q_s[r0 * QSV + d4], ah2, al2);
            split2(q_s[r1 * QSV + d4], ah3, al3);
#pragma unroll
            for (int nb = 0; nb < 8; nb++) {
                // K is [k][d]; B[d][kcol] needed -> kb[kcol * KSK + d]
                unsigned bh0, bh1, bl0, bl1;
                split2(kb[(nb * 8 + gid) * KSK + d0], bh0, bl0);
                split2(kb[(nb * 8 + gid) * KSK + d4], bh1, bl1);
                mma8(acc[nb], ah0, ah1, ah2, ah3, bh0, bh1);
                mma8(acc[nb], ah0, ah1, ah2, ah3, bl0, bl1);
                mma8(acc[nb], al0, al1, al2, al3, bh0, bh1);
            }
        }
        __syncthreads();   // all warps done with kb before it is overwritten

        // Epilogue (gmem only): mask bits, scale, stage raw scores, (m, l)
        const uint2 w0 = *(const uint2*)(mb_r0 + kt * 2);
        const uint2 w1 = *(const uint2*)(mb_r1 + kt * 2);
#pragma unroll
        for (int nb = 0; nb < 8; nb++) {
            const int ct  = nb * 8 + 2 * tig;       // 0..62 within tile
            const unsigned wr0 = (nb < 4) ? w0.x : w0.y;
            const unsigned wr1 = (nb < 4) ? w1.x : w1.y;
            const int sh = ct & 31;
            bool k00 = (wr0 >> sh) & 1u, k01 = (wr0 >> (sh + 1)) & 1u;
            bool k10 = (wr1 >> sh) & 1u, k11 = (wr1 >> (sh + 1)) & 1u;

            float s00 = k00 ? NEG : acc[nb][0] * scale;
            float s01 = k01 ? NEG : acc[nb][1] * scale;
            float s10 = k10 ? NEG : acc[nb][2] * scale;
            float s11 = k11 ? NEG : acc[nb][3] * scale;
            const int col = kt * TK + ct;
            *(float2*)(att + (size_t)r0 * Ss + col) = make_float2(s00, s01);
            *(float2*)(att + (size_t)r1 * Ss + col) = make_float2(s10, s11);

            float nm0 = fmaxf(m0, fmaxf(s00, s01));
            l0 = l0 * __expf(m0 - nm0) + __expf(s00 - nm0) + __expf(s01 - nm0);
            m0 = nm0;
            float nm1 = fmaxf(m1, fmaxf(s10, s11));
            l1 = l1 * __expf(m1 - nm1) + __expf(s10 - nm1) + __expf(s11 - nm1);
            m1 = nm1;
        }
    }

    // ---- Reduce (m, l) across the 4 lanes of each quad ----
#pragma unroll
    for (int off = 1; off <= 2; off <<= 1) {
        float mo  = __shfl_xor_sync(0xffffffffu, m0, off);
        float lo_ = __shfl_xor_sync(0xffffffffu, l0, off);
        float nm = fmaxf(m0, mo);
        l0 = l0 * __expf(m0 - nm) + lo_ * __expf(mo - nm);
        m0 = nm;
        mo  = __shfl_xor_sync(0xffffffffu, m1, off);
        lo_ = __shfl_xor_sync(0xffffffffu, l1, off);
        nm = fmaxf(m1, mo);
        l1 = l1 * __expf(m1 - nm) + lo_ * __expf(mo - nm);
        m1 = nm;
    }
    const float rl0 = 1.0f / l0;
    const float rl1 = 1.0f / l1;

    __syncthreads();    // before overlaying Q region with V buffers

    float* vbuf[2] = {sm + OFF_V0, sm + OFF_V1};
    float* p_s = sm + OFF_P;

    // Prologue: V tile 0 (natural [k][d], stride 72)
#pragma unroll
    for (int i = 0; i < 4; i++) {
        int c = tid + i * NT;
        int row = c >> 4, ch = c & 15;
        cpa16(smem_u32(&vbuf[0][row * TSV + ch * 4]), Vg + row * Dd + ch * 4);
    }
    CPA_COMMIT();

    float cacc[8][4];
#pragma unroll
    for (int n = 0; n < 8; n++)
#pragma unroll
        for (int j = 0; j < 4; j++) cacc[n][j] = 0.0f;

    // ================= Sweep 2: normalize + P·V ============================
    for (int kt = 0; kt < KTILES; kt++) {
        const float* vb = vbuf[kt & 1];
        if (kt + 1 < KTILES) {
            float* nb_ = vbuf[(kt + 1) & 1];
            const float* src = Vg + (size_t)(kt + 1) * TK * Dd;
#pragma unroll
            for (int i = 0; i < 4; i++) {
                int c = tid + i * NT;
                int row = c >> 4, ch = c & 15;
                cpa16(smem_u32(&nb_[row * TSV + ch * 4]), src + row * Dd + ch * 4);
            }
            CPA_COMMIT();
        }

        // Normalize staged scores (gmem) -> att + raw P into smem.
#pragma unroll
        for (int nb = 0; nb < 8; nb++) {
            const int colt = nb * 8 + 2 * tig;
            const int col  = kt * TK + colt;
            float2 s0 = *(const float2*)(att + (size_t)r0 * Ss + col);
            float2 s1 = *(const float2*)(att + (size_t)r1 * Ss + col);
            float p00 = __expf(s0.x - m0) * rl0;
            float p01 = __expf(s0.y - m0) * rl0;
            float p10 = __expf(s1.x - m1) * rl1;
            float p11 = __expf(s1.y - m1) * rl1;
            *(float2*)(att + (size_t)r0 * Ss + col) = make_float2(p00, p01);
            *(float2*)(att + (size_t)r1 * Ss + col) = make_float2(p10, p11);
            *(float2*)&p_s[r0 * QSV + colt] = make_float2(p00, p01);
            *(float2*)&p_s[r1 * QSV + colt] = make_float2(p10, p11);
        }

        if (kt + 1 < KTILES) { CPA_WAIT(1); } else { CPA_WAIT(0); }
        __syncthreads();   // P stores + V tile visible

        // ctx += P(16xTK) @ V(TKx64)
#pragma unroll
        for (int ksi = 0; ksi < 8; ksi++) {
            const int k0 = ksi * 8 + tig;
            const int k4 = k0 + 4;
            unsigned ah0, ah1, ah2, ah3, al0, al1, al2, al3;
            split2(p_s[r0 * QSV + k0], ah0, al0);
            split2(p_s[r1 * QSV + k0], ah1, al1);
            split2(p_s[r0 * QSV + k4], ah2, al2);
            split2(p_s[r1 * QSV + k4], ah3, al3);
#pragma unroll
            for (int nb = 0; nb < 8; nb++) {
                // V is [k][d]; B[k][n] -> vb[k * TSV + n]
                unsigned bh0, bh1, bl0, bl1;
                split2(vb[k0 * TSV + nb * 8 + gid], bh0, bl0);
                split2(vb[k4 * TSV + nb * 8 + gid], bh1, bl1);
                mma8(cacc[nb], ah0, ah1, ah2, ah3, bh0, bh1);
                mma8(cacc[nb], ah0, ah1, ah2, ah3, bl0, bl1);
                mma8(cacc[nb], al0, al1, al2, al3, bh0, bh1);
            }
        }
        __syncthreads();   // done reading p_s / vb before next overwrite
    }

    // ---- Write context ----
#pragma unroll
    for (int nb = 0; nb < 8; nb++) {
        const int col = nb * 8 + 2 * tig;
        *(float2*)(ctx + (size_t)r0 * Dd + col) = make_float2(cacc[nb][0], cacc[nb][1]);
        *(float2*)(ctx + (size_t)r1 * Dd + col) = make_float2(cacc[nb][2], cacc[nb][3]);
    }
}

extern "C" void kernel_launch(void* const* d_in, const int* in_sizes, int n_in,
                              void* d_out, int out_size)
{
    const float* Q = (const float*)d_in[0];
    const float* K = (const float*)d_in[1];
    const float* V = (const float*)d_in[2];
    const void*  M = d_in[3];
    // d_in[4] = dim_key (constant 64), unused

    float* out = (float*)d_out;
    float* ctx = out;                                   // [B,H,S,D]
    float* att = out + (size_t)Bb * Hh * Ss * Dd;       // [B,H,S,S]

    const size_t smem = SMEM_FLOATS * sizeof(float);    // 71680 B
    cudaFuncSetAttribute(attn_mma_kernel,
                         cudaFuncAttributeMaxDynamicSharedMemorySize, (int)smem);

    detect_mask_kernel<<<1, NT>>>((const unsigned int*)M);
    mask_pack_kernel<<<(MASK_WORDS + NT - 1) / NT, NT>>>(M);

    dim3 grid(Ss / TQ, Bb * Hh);                        // (16, 32) = 512 CTAs
    attn_mma_kernel<<<grid, NT, smem>>>(Q, K, V, ctx, att);
}

// round 8
// speedup vs baseline: 2.6859x; 2.6859x over previous
#include <cuda_runtime.h>
#include <math_constants.h>

// Problem constants
#define Bb 2
#define Hh 16
#define Ss 2048
#define Dd 64

// Tiling
#define TQ 128
#define TK 64
#define NT 256
#define KTILES (Ss / TK)        // 32

// smem strides (floats), conflict-free for the fragment access patterns:
//   Q/P [row][col] stride 68: lane addr ≡ gid*4 + tig (mod 32)
//   K   [k][d]    stride 68, read kb[kcol*68 + d]  -> gid*4 + tig
//   V   [k][d]    stride 72, read vb[k*72 + n]     -> tig*8 + gid
#define QSV 68
#define KSK 68
#define TSV 72

// smem layout (floats)
#define OFF_Q   0                        // 128*68 = 8704
#define OFF_K   8704                     // 64*68  = 4352
#define OFF_V   13056                    // 64*72  = 4608
#define OFF_P   17664                    // 128*68 = 8704
#define SMEM_FLOATS 26368                // 105472 B  (2 CTAs/SM fits 228KB)

// mask dtype flag: 1 -> 4-byte elements, 0 -> 1-byte
__device__ int g_mask_elem4;
// packed mask bits: [B, S, S/32]
#define MASK_WORDS (Bb * Ss * (Ss / 32))
__device__ unsigned g_maskbits[MASK_WORDS];
// per-row 1/l for the normalize pass: [B*H*S]
__device__ float g_invl[Bb * Hh * Ss];

__global__ void detect_mask_kernel(const unsigned int* __restrict__ mw)
{
    int has_bigbyte = 0, has_bigword = 0;
    for (int i = threadIdx.x; i < 4096; i += NT) {
        unsigned w = mw[i];
        if ((w & 0xffu) > 1u || ((w >> 8) & 0xffu) > 1u ||
            ((w >> 16) & 0xffu) > 1u || ((w >> 24) & 0xffu) > 1u) has_bigbyte = 1;
        if (w > 1u) has_bigword = 1;
    }
    has_bigbyte = __syncthreads_or(has_bigbyte);
    has_bigword = __syncthreads_or(has_bigword);
    if (threadIdx.x == 0)
        g_mask_elem4 = has_bigbyte ? 1 : (has_bigword ? 0 : 1);
}

__global__ void mask_pack_kernel(const void* __restrict__ mask)
{
    int w = blockIdx.x * blockDim.x + threadIdx.x;
    if (w >= MASK_WORDS) return;
    unsigned bits = 0;
    if (g_mask_elem4) {
        const uint4* p = (const uint4*)mask + (size_t)w * 8;
#pragma unroll
        for (int j = 0; j < 8; j++) {
            uint4 v = p[j];
            bits |= ((unsigned)(v.x != 0u)) << (4 * j);
            bits |= ((unsigned)(v.y != 0u)) << (4 * j + 1);
            bits |= ((unsigned)(v.z != 0u)) << (4 * j + 2);
            bits |= ((unsigned)(v.w != 0u)) << (4 * j + 3);
        }
    } else {
        const uint4* p = (const uint4*)mask + (size_t)w * 2;
#pragma unroll
        for (int j = 0; j < 2; j++) {
            uint4 v = p[j];
            unsigned vv[4] = {v.x, v.y, v.z, v.w};
#pragma unroll
            for (int q = 0; q < 4; q++)
#pragma unroll
                for (int bbit = 0; bbit < 4; bbit++)
                    bits |= ((unsigned)(((vv[q] >> (8 * bbit)) & 0xffu) != 0u))
                            << (16 * j + 4 * q + bbit);
        }
    }
    g_maskbits[w] = bits;
}

__device__ __forceinline__ unsigned f2tf32(float x)
{
    unsigned r;
    asm("cvt.rna.tf32.f32 %0, %1;" : "=r"(r) : "f"(x));
    return r;
}

__device__ __forceinline__ unsigned smem_u32(const void* p)
{
    unsigned r;
    asm("{ .reg .u64 t; cvta.to.shared.u64 t, %1; cvt.u32.u64 %0, t; }"
        : "=r"(r) : "l"(p));
    return r;
}

__device__ __forceinline__ void cpa16(unsigned s, const void* g)
{
    asm volatile("cp.async.cg.shared.global [%0], [%1], 16;" :: "r"(s), "l"(g));
}
#define CPA_COMMIT() asm volatile("cp.async.commit_group;")
#define CPA_WAIT(N)  asm volatile("cp.async.wait_group %0;" :: "n"(N) : "memory")

__device__ __forceinline__ void mma8(float* c,
                                     unsigned a0, unsigned a1, unsigned a2, unsigned a3,
                                     unsigned b0, unsigned b1)
{
    asm volatile(
        "mma.sync.aligned.m16n8k8.row.col.f32.tf32.tf32.f32 "
        "{%0,%1,%2,%3}, {%4,%5,%6,%7}, {%8,%9}, {%0,%1,%2,%3};\n"
        : "+f"(c[0]), "+f"(c[1]), "+f"(c[2]), "+f"(c[3])
        : "r"(a0), "r"(a1), "r"(a2), "r"(a3), "r"(b0), "r"(b1));
}

// split fp32 -> (hi tf32 bits, lo residual bits; HW truncates lo to tf32)
__device__ __forceinline__ void split2(float x, unsigned& hi, unsigned& lo)
{
    hi = f2tf32(x);
    lo = __float_as_uint(x - __uint_as_float(hi));
}

__global__ __launch_bounds__(NT, 2)
void attn_mma_kernel(const float* __restrict__ Qg_,
                     const float* __restrict__ Kg_,
                     const float* __restrict__ Vg_,
                     float* __restrict__ ctx_out,
                     float* __restrict__ att_out)
{
    extern __shared__ float sm[];
    const int tid  = threadIdx.x;
    const int lane = tid & 31;
    const int wid  = tid >> 5;          // 8 warps
    const int gid  = lane >> 2;         // 0..7
    const int tig  = lane & 3;          // 0..3
    const int r0   = wid * 16 + gid;    // local q rows
    const int r1   = r0 + 8;

    const int qt = blockIdx.x;
    const int bh = blockIdx.y;
    const int b  = bh >> 4;
    const int q0 = qt * TQ;

    const size_t head_off = (size_t)bh * Ss * Dd;
    const float* Qg = Qg_ + head_off + (size_t)q0 * Dd;
    const float* Kg = Kg_ + head_off;
    const float* Vg = Vg_ + head_off;
    float* att = att_out + (size_t)bh * Ss * Ss + (size_t)q0 * Ss;
    float* ctx = ctx_out + head_off + (size_t)q0 * Dd;
    const unsigned* mb_r0 = g_maskbits + ((size_t)b * Ss + q0 + r0) * (Ss / 32);
    const unsigned* mb_r1 = g_maskbits + ((size_t)b * Ss + q0 + r1) * (Ss / 32);

    const float scale = 0.125f;     // 1/sqrt(64)

    float* q_s = sm + OFF_Q;
    float* kb  = sm + OFF_K;
    float* vb  = sm + OFF_V;
    float* p_s = sm + OFF_P;

    // ---- Prologue: async-copy Q tile + K tile 0 (one group) ----
    {
#pragma unroll
        for (int i = 0; i < 8; i++) {
            int c = tid + i * NT;
            int row = c >> 4, ch = c & 15;
            cpa16(smem_u32(&q_s[row * QSV + ch * 4]), Qg + row * Dd + ch * 4);
        }
#pragma unroll
        for (int i = 0; i < 4; i++) {
            int c = tid + i * NT;
            int row = c >> 4, ch = c & 15;
            cpa16(smem_u32(&kb[row * KSK + ch * 4]), Kg + row * Dd + ch * 4);
        }
        CPA_COMMIT();
    }

    float l0 = 0.0f, l1 = 0.0f;          // unnormalized row sums
    float cacc[8][4];                    // O accumulator (unnormalized)
#pragma unroll
    for (int n = 0; n < 8; n++)
#pragma unroll
        for (int j = 0; j < 4; j++) cacc[n][j] = 0.0f;

    // ================= Single fused sweep =================
    for (int kt = 0; kt < KTILES; kt++) {
        // Issue V(kt) copy — overlaps the S-MMA phase below.
        {
            const float* src = Vg + (size_t)kt * TK * Dd;
#pragma unroll
            for (int i = 0; i < 4; i++) {
                int c = tid + i * NT;
                int row = c >> 4, ch = c & 15;
                cpa16(smem_u32(&vb[row * TSV + ch * 4]), src + row * Dd + ch * 4);
            }
            CPA_COMMIT();
        }
        CPA_WAIT(1);        // K(kt) (and Q) complete; V(kt) still in flight
        __syncthreads();    // kb visible to all; prev iter's p_s/vb reads done

        // Prefetch mask words (consumed in epilogue)
        const uint2 w0 = *(const uint2*)(mb_r0 + kt * 2);
        const uint2 w1 = *(const uint2*)(mb_r1 + kt * 2);

        // ---- S = Q K^T on this tile ----
        float sacc[8][4];
#pragma unroll
        for (int n = 0; n < 8; n++)
#pragma unroll
            for (int j = 0; j < 4; j++) sacc[n][j] = 0.0f;

#pragma unroll
        for (int ksi = 0; ksi < 8; ksi++) {
            const int d0 = ksi * 8 + tig;
            const int d4 = d0 + 4;
            unsigned ah0, ah1, ah2, ah3, al0, al1, al2, al3;
            split2(q_s[r0 * QSV + d0], ah0, al0);
            split2(q_s[r1 * QSV + d0], ah1, al1);
            split2(q_s[r0 * QSV + d4], ah2, al2);
            split2(q_s[r1 * QSV + d4], ah3, al3);
#pragma unroll
            for (int h = 0; h < 2; h++) {
                unsigned bh0[4], bh1[4], bl0[4], bl1[4];
#pragma unroll
                for (int j = 0; j < 4; j++) {
                    const int nb = h * 4 + j;
                    split2(kb[(nb * 8 + gid) * KSK + d0], bh0[j], bl0[j]);
                    split2(kb[(nb * 8 + gid) * KSK + d4], bh1[j], bl1[j]);
                }
                // pass-major: 4 independent MMAs per pass
#pragma unroll
                for (int j = 0; j < 4; j++)
                    mma8(sacc[h * 4 + j], ah0, ah1, ah2, ah3, bh0[j], bh1[j]);
#pragma unroll
                for (int j = 0; j < 4; j++)
                    mma8(sacc[h * 4 + j], al0, al1, al2, al3, bh0[j], bh1[j]);
#pragma unroll
                for (int j = 0; j < 4; j++)
                    mma8(sacc[h * 4 + j], ah0, ah1, ah2, ah3, bl0[j], bl1[j]);
            }
        }

        // ---- Epilogue: e = mask ? 0 : exp(s*scale); att + p_s + l ----
#pragma unroll
        for (int nb = 0; nb < 8; nb++) {
            const int ct  = nb * 8 + 2 * tig;
            const unsigned wr0 = (nb < 4) ? w0.x : w0.y;
            const unsigned wr1 = (nb < 4) ? w1.x : w1.y;
            const int sh = ct & 31;
            float e00 = ((wr0 >> sh) & 1u)       ? 0.0f : __expf(sacc[nb][0] * scale);
            float e01 = ((wr0 >> (sh + 1)) & 1u) ? 0.0f : __expf(sacc[nb][1] * scale);
            float e10 = ((wr1 >> sh) & 1u)       ? 0.0f : __expf(sacc[nb][2] * scale);
            float e11 = ((wr1 >> (sh + 1)) & 1u) ? 0.0f : __expf(sacc[nb][3] * scale);

            const int col = kt * TK + ct;
            *(float2*)(att + (size_t)r0 * Ss + col) = make_float2(e00, e01);
            *(float2*)(att + (size_t)r1 * Ss + col) = make_float2(e10, e11);
            *(float2*)&p_s[r0 * QSV + ct] = make_float2(e00, e01);
            *(float2*)&p_s[r1 * QSV + ct] = make_float2(e10, e11);
            l0 += e00 + e01;
            l1 += e10 + e11;
        }
        __syncthreads();    // p_s complete; kb free for next tile

        // Issue K(kt+1) copy — overlaps the PV phase.
        if (kt + 1 < KTILES) {
            const float* src = Kg + (size_t)(kt + 1) * TK * Dd;
#pragma unroll
            for (int i = 0; i < 4; i++) {
                int c = tid + i * NT;
                int row = c >> 4, ch = c & 15;
                cpa16(smem_u32(&kb[row * KSK + ch * 4]), src + row * Dd + ch * 4);
            }
            CPA_COMMIT();
            CPA_WAIT(1);    // V(kt) complete; K(kt+1) in flight
        } else {
            CPA_WAIT(0);
        }
        __syncwarp();

        // ---- O += P V on this tile ----
#pragma unroll
        for (int ksi = 0; ksi < 8; ksi++) {
            const int k0 = ksi * 8 + tig;
            const int k4 = k0 + 4;
            unsigned ah0, ah1, ah2, ah3, al0, al1, al2, al3;
            split2(p_s[r0 * QSV + k0], ah0, al0);
            split2(p_s[r1 * QSV + k0], ah1, al1);
            split2(p_s[r0 * QSV + k4], ah2, al2);
            split2(p_s[r1 * QSV + k4], ah3, al3);
#pragma unroll
            for (int h = 0; h < 2; h++) {
                unsigned bh0[4], bh1[4], bl0[4], bl1[4];
#pragma unroll
                for (int j = 0; j < 4; j++) {
                    const int nb = h * 4 + j;
                    split2(vb[k0 * TSV + nb * 8 + gid], bh0[j], bl0[j]);
                    split2(vb[k4 * TSV + nb * 8 + gid], bh1[j], bl1[j]);
                }
#pragma unroll
                for (int j = 0; j < 4; j++)
                    mma8(cacc[h * 4 + j], ah0, ah1, ah2, ah3, bh0[j], bh1[j]);
#pragma unroll
                for (int j = 0; j < 4; j++)
                    mma8(cacc[h * 4 + j], al0, al1, al2, al3, bh0[j], bh1[j]);
#pragma unroll
                for (int j = 0; j < 4; j++)
                    mma8(cacc[h * 4 + j], ah0, ah1, ah2, ah3, bl0[j], bl1[j]);
            }
        }
        __syncthreads();    // vb + p_s reads done before next overwrite
    }

    // ---- Reduce l across the quad; write 1/l; write ctx = O/l ----
#pragma unroll
    for (int off = 1; off <= 2; off <<= 1) {
        l0 += __shfl_xor_sync(0xffffffffu, l0, off);
        l1 += __shfl_xor_sync(0xffffffffu, l1, off);
    }
    const float inv0 = 1.0f / l0;
    const float inv1 = 1.0f / l1;
    if (tig == 0) {
        g_invl[(size_t)bh * Ss + q0 + r0] = inv0;
        g_invl[(size_t)bh * Ss + q0 + r1] = inv1;
    }

#pragma unroll
    for (int nb = 0; nb < 8; nb++) {
        const int col = nb * 8 + 2 * tig;
        *(float2*)(ctx + (size_t)r0 * Dd + col) =
            make_float2(cacc[nb][0] * inv0, cacc[nb][1] * inv0);
        *(float2*)(ctx + (size_t)r1 * Dd + col) =
            make_float2(cacc[nb][2] * inv1, cacc[nb][3] * inv1);
    }
}

// Streaming normalize: att[row][k] *= 1/l[row]
__global__ void att_norm_kernel(float4* __restrict__ att4)
{
    const size_t total4 = (size_t)Bb * Hh * Ss * Ss / 4;   // 33554432
    size_t i = (size_t)blockIdx.x * blockDim.x + threadIdx.x;
    const size_t stride = (size_t)gridDim.x * blockDim.x;
    for (size_t j = i; j < total4; j += stride) {
        const float inv = g_invl[j >> 9];      // 512 float4 per row
        float4 v = att4[j];
        v.x *= inv; v.y *= inv; v.z *= inv; v.w *= inv;
        att4[j] = v;
    }
}

extern "C" void kernel_launch(void* const* d_in, const int* in_sizes, int n_in,
                              void* d_out, int out_size)
{
    const float* Q = (const float*)d_in[0];
    const float* K = (const float*)d_in[1];
    const float* V = (const float*)d_in[2];
    const void*  M = d_in[3];
    // d_in[4] = dim_key (constant 64), unused

    float* out = (float*)d_out;
    float* ctx = out;                                   // [B,H,S,D]
    float* att = out + (size_t)Bb * Hh * Ss * Dd;       // [B,H,S,S]

    const size_t smem = SMEM_FLOATS * sizeof(float);    // 105472 B
    cudaFuncSetAttribute(attn_mma_kernel,
                         cudaFuncAttributeMaxDynamicSharedMemorySize, (int)smem);

    detect_mask_kernel<<<1, NT>>>((const unsigned int*)M);
    mask_pack_kernel<<<(MASK_WORDS + NT - 1) / NT, NT>>>(M);

    dim3 grid(Ss / TQ, Bb * Hh);                        // (16, 32) = 512 CTAs
    attn_mma_kernel<<<grid, NT, smem>>>(Q, K, V, ctx, att);

    att_norm_kernel<<<2048, 256>>>((float4*)att);
}

// round 10
// speedup vs baseline: 2.8601x; 1.0649x over previous
#include <cuda_runtime.h>
#include <math_constants.h>

// Problem constants
#define Bb 2
#define Hh 16
#define Ss 2048
#define Dd 64

// Tiling: CTA = 64 q-rows x full K sweep; warp pair shares a 64-col tile half
#define TQ 64
#define TK 64
#define NT 256
#define KTILES (Ss / TK)        // 32

// smem strides (floats), conflict-free fragment access:
//   Q/P [row][col] stride 68: lane addr ≡ gid*4 + tig (mod 32)
//   K   [k][d]    stride 68, read kb[kcol*68 + d]  -> gid*4 + tig
//   V   [k][d]    stride 72, read vb[k*72 + n]     -> tig*8 + gid
#define QSV 68
#define KSK 68
#define TSV 72

// smem layout (floats)
#define OFF_Q   0                        // 64*68 = 4352
#define OFF_K   4352                     // 64*68 = 4352
#define OFF_V   8704                     // 64*72 = 4608
#define OFF_P   13312                    // 64*68 = 4352
#define SMEM_FLOATS 17664                // 70656 B -> 3 CTAs/SM

// mask dtype flag: 1 -> 4-byte elements, 0 -> 1-byte
__device__ int g_mask_elem4;
// packed mask bits: [B, S, S/32]
#define MASK_WORDS (Bb * Ss * (Ss / 32))
__device__ unsigned g_maskbits[MASK_WORDS];
// per-row 1/l for the normalize pass: [B*H*S]
__device__ float g_invl[Bb * Hh * Ss];

__global__ void detect_mask_kernel(const unsigned int* __restrict__ mw)
{
    int has_bigbyte = 0, has_bigword = 0;
    for (int i = threadIdx.x; i < 4096; i += NT) {
        unsigned w = mw[i];
        if ((w & 0xffu) > 1u || ((w >> 8) & 0xffu) > 1u ||
            ((w >> 16) & 0xffu) > 1u || ((w >> 24) & 0xffu) > 1u) has_bigbyte = 1;
        if (w > 1u) has_bigword = 1;
    }
    has_bigbyte = __syncthreads_or(has_bigbyte);
    has_bigword = __syncthreads_or(has_bigword);
    if (threadIdx.x == 0)
        g_mask_elem4 = has_bigbyte ? 1 : (has_bigword ? 0 : 1);
}

__global__ void mask_pack_kernel(const void* __restrict__ mask)
{
    int w = blockIdx.x * blockDim.x + threadIdx.x;
    if (w >= MASK_WORDS) return;
    unsigned bits = 0;
    if (g_mask_elem4) {
        const uint4* p = (const uint4*)mask + (size_t)w * 8;
#pragma unroll
        for (int j = 0; j < 8; j++) {
            uint4 v = p[j];
            bits |= ((unsigned)(v.x != 0u)) << (4 * j);
            bits |= ((unsigned)(v.y != 0u)) << (4 * j + 1);
            bits |= ((unsigned)(v.z != 0u)) << (4 * j + 2);
            bits |= ((unsigned)(v.w != 0u)) << (4 * j + 3);
        }
    } else {
        const uint4* p = (const uint4*)mask + (size_t)w * 2;
#pragma unroll
        for (int j = 0; j < 2; j++) {
            uint4 v = p[j];
            unsigned vv[4] = {v.x, v.y, v.z, v.w};
#pragma unroll
            for (int q = 0; q < 4; q++)
#pragma unroll
                for (int bbit = 0; bbit < 4; bbit++)
                    bits |= ((unsigned)(((vv[q] >> (8 * bbit)) & 0xffu) != 0u))
                            << (16 * j + 4 * q + bbit);
        }
    }
    g_maskbits[w] = bits;
}

__device__ __forceinline__ unsigned f2tf32(float x)
{
    unsigned r;
    asm("cvt.rna.tf32.f32 %0, %1;" : "=r"(r) : "f"(x));
    return r;
}

__device__ __forceinline__ unsigned smem_u32(const void* p)
{
    unsigned r;
    asm("{ .reg .u64 t; cvta.to.shared.u64 t, %1; cvt.u32.u64 %0, t; }"
        : "=r"(r) : "l"(p));
    return r;
}

__device__ __forceinline__ void cpa16(unsigned s, const void* g)
{
    asm volatile("cp.async.cg.shared.global [%0], [%1], 16;" :: "r"(s), "l"(g));
}
#define CPA_COMMIT() asm volatile("cp.async.commit_group;")
#define CPA_WAIT(N)  asm volatile("cp.async.wait_group %0;" :: "n"(N) : "memory")

__device__ __forceinline__ void mma8(float* c,
                                     unsigned a0, unsigned a1, unsigned a2, unsigned a3,
                                     unsigned b0, unsigned b1)
{
    asm volatile(
        "mma.sync.aligned.m16n8k8.row.col.f32.tf32.tf32.f32 "
        "{%0,%1,%2,%3}, {%4,%5,%6,%7}, {%8,%9}, {%0,%1,%2,%3};\n"
        : "+f"(c[0]), "+f"(c[1]), "+f"(c[2]), "+f"(c[3])
        : "r"(a0), "r"(a1), "r"(a2), "r"(a3), "r"(b0), "r"(b1));
}

// split fp32 -> (hi tf32 bits, lo residual bits; HW truncates lo to tf32)
__device__ __forceinline__ void split2(float x, unsigned& hi, unsigned& lo)
{
    hi = f2tf32(x);
    lo = __float_as_uint(x - __uint_as_float(hi));
}

__global__ __launch_bounds__(NT, 3)
void attn_mma_kernel(const float* __restrict__ Qg_,
                     const float* __restrict__ Kg_,
                     const float* __restrict__ Vg_,
                     float* __restrict__ ctx_out,
                     float* __restrict__ att_out)
{
    extern __shared__ float sm[];
    const int tid  = threadIdx.x;
    const int lane = tid & 31;
    const int wid  = tid >> 5;          // 8 warps
    const int gid  = lane >> 2;         // 0..7
    const int tig  = lane & 3;          // 0..3
    const int wrow = wid >> 1;          // 0..3 : which 16-row block
    const int wcol = wid & 1;           // 0..1 : which 32-col half
    const int cb   = wcol * 32;         // col base within 64-wide tile
    const int r0   = wrow * 16 + gid;   // local q rows
    const int r1   = r0 + 8;

    const int qt = blockIdx.x;
    const int bh = blockIdx.y;
    const int b  = bh >> 4;
    const int q0 = qt * TQ;

    const size_t head_off = (size_t)bh * Ss * Dd;
    const float* Qg = Qg_ + head_off + (size_t)q0 * Dd;
    const float* Kg = Kg_ + head_off;
    const float* Vg = Vg_ + head_off;
    float* att = att_out + (size_t)bh * Ss * Ss + (size_t)q0 * Ss;
    float* ctx = ctx_out + head_off + (size_t)q0 * Dd;
    const unsigned* mb_r0 = g_maskbits + ((size_t)b * Ss + q0 + r0) * (Ss / 32);
    const unsigned* mb_r1 = g_maskbits + ((size_t)b * Ss + q0 + r1) * (Ss / 32);

    const float scale = 0.125f;     // 1/sqrt(64)

    float* q_s = sm + OFF_Q;
    float* kb  = sm + OFF_K;
    float* vb  = sm + OFF_V;
    float* p_s = sm + OFF_P;

    // ---- Prologue: async-copy Q tile + K tile 0 (one group) ----
    {
#pragma unroll
        for (int i = 0; i < 4; i++) {
            int c = tid + i * NT;
            int row = c >> 4, ch = c & 15;
            cpa16(smem_u32(&q_s[row * QSV + ch * 4]), Qg + row * Dd + ch * 4);
        }
#pragma unroll
        for (int i = 0; i < 4; i++) {
            int c = tid + i * NT;
            int row = c >> 4, ch = c & 15;
            cpa16(smem_u32(&kb[row * KSK + ch * 4]), Kg + row * Dd + ch * 4);
        }
        CPA_COMMIT();
    }

    float l0 = 0.0f, l1 = 0.0f;          // row sums over this warp's 32 cols
    float cacc[4][4];                    // O accumulator (16 rows x 32 d-cols)
#pragma unroll
    for (int n = 0; n < 4; n++)
#pragma unroll
        for (int j = 0; j < 4; j++) cacc[n][j] = 0.0f;

    // ================= Single fused sweep =================
    for (int kt = 0; kt < KTILES; kt++) {
        // Issue V(kt) copy — overlaps the S-MMA phase below.
        {
            const float* src = Vg + (size_t)kt * TK * Dd;
#pragma unroll
            for (int i = 0; i < 4; i++) {
                int c = tid + i * NT;
                int row = c >> 4, ch = c & 15;
                cpa16(smem_u32(&vb[row * TSV + ch * 4]), src + row * Dd + ch * 4);
            }
            CPA_COMMIT();
        }
        CPA_WAIT(1);        // K(kt) (and Q) complete; V(kt) still in flight
        __syncthreads();    // kb visible; prev iter's p_s/vb reads done

        // Prefetch mask words for this warp's 32-col half
        const unsigned w0 = mb_r0[kt * 2 + wcol];
        const unsigned w1 = mb_r1[kt * 2 + wcol];

        // ---- S = Q K^T on this warp's 16x32 patch ----
        float sacc[4][4];
#pragma unroll
        for (int n = 0; n < 4; n++)
#pragma unroll
            for (int j = 0; j < 4; j++) sacc[n][j] = 0.0f;

#pragma unroll
        for (int ksi = 0; ksi < 8; ksi++) {
            const int d0 = ksi * 8 + tig;
            const int d4 = d0 + 4;
            unsigned ah0, ah1, ah2, ah3, al0, al1, al2, al3;
            split2(q_s[r0 * QSV + d0], ah0, al0);
            split2(q_s[r1 * QSV + d0], ah1, al1);
            split2(q_s[r0 * QSV + d4], ah2, al2);
            split2(q_s[r1 * QSV + d4], ah3, al3);
            unsigned bh0[4], bh1[4], bl0[4], bl1[4];
#pragma unroll
            for (int j = 0; j < 4; j++) {
                const int col = cb + j * 8 + gid;
                split2(kb[col * KSK + d0], bh0[j], bl0[j]);
                split2(kb[col * KSK + d4], bh1[j], bl1[j]);
            }
#pragma unroll
            for (int j = 0; j < 4; j++)
                mma8(sacc[j], ah0, ah1, ah2, ah3, bh0[j], bh1[j]);
#pragma unroll
            for (int j = 0; j < 4; j++)
                mma8(sacc[j], al0, al1, al2, al3, bh0[j], bh1[j]);
#pragma unroll
            for (int j = 0; j < 4; j++)
                mma8(sacc[j], ah0, ah1, ah2, ah3, bl0[j], bl1[j]);
        }

        // ---- Epilogue: e = mask ? 0 : exp(s*scale); att + p_s + l ----
#pragma unroll
        for (int nb = 0; nb < 4; nb++) {
            const int ct = nb * 8 + 2 * tig;       // 0..30 within half
            float e00 = ((w0 >> ct) & 1u)       ? 0.0f : __expf(sacc[nb][0] * scale);
            float e01 = ((w0 >> (ct + 1)) & 1u) ? 0.0f : __expf(sacc[nb][1] * scale);
            float e10 = ((w1 >> ct) & 1u)       ? 0.0f : __expf(sacc[nb][2] * scale);
            float e11 = ((w1 >> (ct + 1)) & 1u) ? 0.0f : __expf(sacc[nb][3] * scale);

            const int col = kt * TK + cb + ct;
            *(float2*)(att + (size_t)r0 * Ss + col) = make_float2(e00, e01);
            *(float2*)(att + (size_t)r1 * Ss + col) = make_float2(e10, e11);
            *(float2*)&p_s[r0 * QSV + cb + ct] = make_float2(e00, e01);
            *(float2*)&p_s[r1 * QSV + cb + ct] = make_float2(e10, e11);
            l0 += e00 + e01;
            l1 += e10 + e11;
        }
        __syncthreads();    // p_s complete; kb free for next tile

        // Issue K(kt+1) copy — overlaps the PV phase.
        if (kt + 1 < KTILES) {
            const float* src = Kg + (size_t)(kt + 1) * TK * Dd;
#pragma unroll
            for (int i = 0; i < 4; i++) {
                int c = tid + i * NT;
                int row = c >> 4, ch = c & 15;
                cpa16(smem_u32(&kb[row * KSK + ch * 4]), src + row * Dd + ch * 4);
            }
            CPA_COMMIT();
            CPA_WAIT(1);    // V(kt) complete; K(kt+1) in flight
        } else {
            CPA_WAIT(0);
        }
        __syncwarp();

        // ---- O += P V : contract over all 64 k, output this warp's 32 d ----
#pragma unroll
        for (int ksi = 0; ksi < 8; ksi++) {
            const int k0 = ksi * 8 + tig;
            const int k4 = k0 + 4;
            unsigned ah0, ah1, ah2, ah3, al0, al1, al2, al3;
            split2(p_s[r0 * QSV + k0], ah0, al0);
            split2(p_s[r1 * QSV + k0], ah1, al1);
            split2(p_s[r0 * QSV + k4], ah2, al2);
            split2(p_s[r1 * QSV + k4], ah3, al3);
            unsigned bh0[4], bh1[4], bl0[4], bl1[4];
#pragma unroll
            for (int j = 0; j < 4; j++) {
                const int n = cb + j * 8 + gid;
                split2(vb[k0 * TSV + n], bh0[j], bl0[j]);
                split2(vb[k4 * TSV + n], bh1[j], bl1[j]);
            }
#pragma unroll
            for (int j = 0; j < 4; j++)
                mma8(cacc[j], ah0, ah1, ah2, ah3, bh0[j], bh1[j]);
#pragma unroll
            for (int j = 0; j < 4; j++)
                mma8(cacc[j], al0, al1, al2, al3, bh0[j], bh1[j]);
#pragma unroll
            for (int j = 0; j < 4; j++)
                mma8(cacc[j], ah0, ah1, ah2, ah3, bl0[j], bl1[j]);
        }
        __syncthreads();    // vb + p_s reads done before next overwrite
    }

    // ---- Finalize l: quad reduce, then combine the two col-halves ----
#pragma unroll
    for (int off = 1; off <= 2; off <<= 1) {
        l0 += __shfl_xor_sync(0xffffffffu, l0, off);
        l1 += __shfl_xor_sync(0xffffffffu, l1, off);
    }
    float* red = kb;    // reuse K buffer (all cp.async drained, post-barrier)
    if (tig == 0) {
        red[r0 * 2 + wcol] = l0;
        red[r1 * 2 + wcol] = l1;
    }
    __syncthreads();
    const float inv0 = 1.0f / (red[r0 * 2] + red[r0 * 2 + 1]);
    const float inv1 = 1.0f / (red[r1 * 2] + red[r1 * 2 + 1]);
    if (wcol == 0 && tig == 0) {
        g_invl[(size_t)bh * Ss + q0 + r0] = inv0;
        g_invl[(size_t)bh * Ss + q0 + r1] = inv1;
    }

    // ---- Write context = O / l ----
#pragma unroll
    for (int nb = 0; nb < 4; nb++) {
        const int col = cb + nb * 8 + 2 * tig;
        *(float2*)(ctx + (size_t)r0 * Dd + col) =
            make_float2(cacc[nb][0] * inv0, cacc[nb][1] * inv0);
        *(float2*)(ctx + (size_t)r1 * Dd + col) =
            make_float2(cacc[nb][2] * inv1, cacc[nb][3] * inv1);
    }
}

// Streaming normalize: att[row][k] *= 1/l[row]
__global__ void att_norm_kernel(float4* __restrict__ att4)
{
    const size_t total4 = (size_t)Bb * Hh * Ss * Ss / 4;   // 33554432
    size_t i = (size_t)blockIdx.x * blockDim.x + threadIdx.x;
    const size_t stride = (size_t)gridDim.x * blockDim.x;
    for (size_t j = i; j < total4; j += stride) {
        const float inv = g_invl[j >> 9];      // 512 float4 per row
        float4 v = att4[j];
        v.x *= inv; v.y *= inv; v.z *= inv; v.w *= inv;
        att4[j] = v;
    }
}

extern "C" void kernel_launch(void* const* d_in, const int* in_sizes, int n_in,
                              void* d_out, int out_size)
{
    const float* Q = (const float*)d_in[0];
    const float* K = (const float*)d_in[1];
    const float* V = (const float*)d_in[2];
    const void*  M = d_in[3];
    // d_in[4] = dim_key (constant 64), unused

    float* out = (float*)d_out;
    float* ctx = out;                                   // [B,H,S,D]
    float* att = out + (size_t)Bb * Hh * Ss * Dd;       // [B,H,S,S]

    const size_t smem = SMEM_FLOATS * sizeof(float);    // 70656 B
    cudaFuncSetAttribute(attn_mma_kernel,
                         cudaFuncAttributeMaxDynamicSharedMemorySize, (int)smem);

    detect_mask_kernel<<<1, NT>>>((const unsigned int*)M);
    mask_pack_kernel<<<(MASK_WORDS + NT - 1) / NT, NT>>>(M);

    dim3 grid(Ss / TQ, Bb * Hh);                        // (32, 32) = 1024 CTAs
    attn_mma_kernel<<<grid, NT, smem>>>(Q, K, V, ctx, att);

    att_norm_kernel<<<2048, 256>>>((float4*)att);
}

// round 14
// speedup vs baseline: 3.4682x; 1.2126x over previous
#include <cuda_runtime.h>
#include <math_constants.h>

// Problem constants
#define Bb 2
#define Hh 16
#define Ss 2048
#define Dd 64

// Tiling: CTA = 64 q-rows, 8 warps, warp tile 16 rows x 32 cols
#define TQ 64
#define TK 64
#define NT 256
#define KTILES (Ss / TK)        // 32

// bf16 arrays: stride 72 bf16 (=36 words): fragment lane bank = 4*gid+tig (perm)
#define BS 72
#define BSW 36                  // 32-bit words per row
// raw fp32 staging stride
#define RS 68

// smem layout in floats (4B units)
#define OFF_QH   0              // 64*36 = 2304 words each
#define OFF_QL   2304
#define OFF_KH   4608
#define OFF_KL   6912
#define OFF_VTH  9216
#define OFF_VTL  11520
#define OFF_PH   13824
#define OFF_PL   16128
#define OFF_KRAW 18432          // 64*68 = 4352 floats
#define OFF_VRAW 22784          // 4352 (aliases Q raw in prologue)
#define SMEM_FLOATS 27136       // 108544 B -> 2 CTAs/SM

// mask dtype flag: 1 -> 4-byte elements, 0 -> 1-byte
__device__ int g_mask_elem4;
// packed mask bits: [B, S, S/32]
#define MASK_WORDS (Bb * Ss * (Ss / 32))
__device__ unsigned g_maskbits[MASK_WORDS];
// per-row 1/l for the normalize pass: [B*H*S]
__device__ float g_invl[Bb * Hh * Ss];

__global__ void detect_mask_kernel(const unsigned int* __restrict__ mw)
{
    int has_bigbyte = 0, has_bigword = 0;
    for (int i = threadIdx.x; i < 4096; i += NT) {
        unsigned w = mw[i];
        if ((w & 0xffu) > 1u || ((w >> 8) & 0xffu) > 1u ||
            ((w >> 16) & 0xffu) > 1u || ((w >> 24) & 0xffu) > 1u) has_bigbyte = 1;
        if (w > 1u) has_bigword = 1;
    }
    has_bigbyte = __syncthreads_or(has_bigbyte);
    has_bigword = __syncthreads_or(has_bigword);
    if (threadIdx.x == 0)
        g_mask_elem4 = has_bigbyte ? 1 : (has_bigword ? 0 : 1);
}

__global__ void mask_pack_kernel(const void* __restrict__ mask)
{
    int w = blockIdx.x * blockDim.x + threadIdx.x;
    if (w >= MASK_WORDS) return;
    unsigned bits = 0;
    if (g_mask_elem4) {
        const uint4* p = (const uint4*)mask + (size_t)w * 8;
#pragma unroll
        for (int j = 0; j < 8; j++) {
            uint4 v = p[j];
            bits |= ((unsigned)(v.x != 0u)) << (4 * j);
            bits |= ((unsigned)(v.y != 0u)) << (4 * j + 1);
            bits |= ((unsigned)(v.z != 0u)) << (4 * j + 2);
            bits |= ((unsigned)(v.w != 0u)) << (4 * j + 3);
        }
    } else {
        const uint4* p = (const uint4*)mask + (size_t)w * 2;
#pragma unroll
        for (int j = 0; j < 2; j++) {
            uint4 v = p[j];
            unsigned vv[4] = {v.x, v.y, v.z, v.w};
#pragma unroll
            for (int q = 0; q < 4; q++)
#pragma unroll
                for (int bbit = 0; bbit < 4; bbit++)
                    bits |= ((unsigned)(((vv[q] >> (8 * bbit)) & 0xffu) != 0u))
                            << (16 * j + 4 * q + bbit);
        }
    }
    g_maskbits[w] = bits;
}

__device__ __forceinline__ unsigned smem_u32(const void* p)
{
    unsigned r;
    asm("{ .reg .u64 t; cvta.to.shared.u64 t, %1; cvt.u32.u64 %0, t; }"
        : "=r"(r) : "l"(p));
    return r;
}

__device__ __forceinline__ void cpa16(unsigned s, const void* g)
{
    asm volatile("cp.async.cg.shared.global [%0], [%1], 16;" :: "r"(s), "l"(g));
}
#define CPA_COMMIT() asm volatile("cp.async.commit_group;")
#define CPA_WAIT(N)  asm volatile("cp.async.wait_group %0;" :: "n"(N) : "memory")

// pack two f32 into bf16x2: element "x0" -> low half, "x1" -> high half.
// (A globally consistent order is self-cancelling inside the MMA dot product.)
__device__ __forceinline__ unsigned pack2(float x0, float x1)
{
    unsigned r;
    asm("cvt.rn.bf16x2.f32 %0, %1, %2;" : "=r"(r) : "f"(x1), "f"(x0));
    return r;
}

// split a pair (x0 = even k, x1 = odd k) into packed hi & lo bf16x2
__device__ __forceinline__ void split_pair(float x0, float x1,
                                           unsigned& hi, unsigned& lo)
{
    hi = pack2(x0, x1);
    float h0 = __uint_as_float(hi << 16);
    float h1 = __uint_as_float(hi & 0xffff0000u);
    lo = pack2(x0 - h0, x1 - h1);
}

__device__ __forceinline__ void mma16(float* c,
                                      unsigned a0, unsigned a1, unsigned a2, unsigned a3,
                                      unsigned b0, unsigned b1)
{
    asm volatile(
        "mma.sync.aligned.m16n8k16.row.col.f32.bf16.bf16.f32 "
        "{%0,%1,%2,%3}, {%4,%5,%6,%7}, {%8,%9}, {%0,%1,%2,%3};\n"
        : "+f"(c[0]), "+f"(c[1]), "+f"(c[2]), "+f"(c[3])
        : "r"(a0), "r"(a1), "r"(a2), "r"(a3), "r"(b0), "r"(b1));
}

__global__ __launch_bounds__(NT, 2)
void attn_mma_kernel(const float* __restrict__ Qg_,
                     const float* __restrict__ Kg_,
                     const float* __restrict__ Vg_,
                     float* __restrict__ ctx_out,
                     float* __restrict__ att_out)
{
    extern __shared__ float sm[];
    const int tid  = threadIdx.x;
    const int lane = tid & 31;
    const int wid  = tid >> 5;          // 8 warps
    const int gid  = lane >> 2;         // 0..7
    const int tig  = lane & 3;          // 0..3
    const int wrow = wid >> 1;          // 0..3
    const int wcol = wid & 1;           // 0..1
    const int cb   = wcol * 32;         // col base within 64-wide tile
    const int r0   = wrow * 16 + gid;
    const int r1   = r0 + 8;

    const int qt = blockIdx.x;
    const int bh = blockIdx.y;
    const int b  = bh >> 4;
    const int q0 = qt * TQ;

    const size_t head_off = (size_t)bh * Ss * Dd;
    const float* Qg = Qg_ + head_off + (size_t)q0 * Dd;
    const float* Kg = Kg_ + head_off;
    const float* Vg = Vg_ + head_off;
    float* att = att_out + (size_t)bh * Ss * Ss + (size_t)q0 * Ss;
    float* ctx = ctx_out + head_off + (size_t)q0 * Dd;
    const unsigned* mb_r0 = g_maskbits + ((size_t)b * Ss + q0 + r0) * (Ss / 32);
    const unsigned* mb_r1 = g_maskbits + ((size_t)b * Ss + q0 + r1) * (Ss / 32);

    const float scale = 0.125f;     // 1/sqrt(64)

    unsigned* QH = (unsigned*)(sm + OFF_QH);
    unsigned* QL = (unsigned*)(sm + OFF_QL);
    unsigned* KH = (unsigned*)(sm + OFF_KH);
    unsigned* KL = (unsigned*)(sm + OFF_KL);
    unsigned* VTH = (unsigned*)(sm + OFF_VTH);
    unsigned* VTL = (unsigned*)(sm + OFF_VTL);
    unsigned* PH = (unsigned*)(sm + OFF_PH);
    unsigned* PL = (unsigned*)(sm + OFF_PL);
    float* KRAW = sm + OFF_KRAW;
    float* VRAW = sm + OFF_VRAW;    // doubles as Q raw in prologue

    // ---- Prologue: cp.async Q raw (into VRAW) + K0 raw; split Q ----
#pragma unroll
    for (int i = 0; i < 4; i++) {
        int c = tid + i * NT;
        int row = c >> 4, ch = c & 15;
        cpa16(smem_u32(&VRAW[row * RS + ch * 4]), Qg + row * Dd + ch * 4);
    }
#pragma unroll
    for (int i = 0; i < 4; i++) {
        int c = tid + i * NT;
        int row = c >> 4, ch = c & 15;
        cpa16(smem_u32(&KRAW[row * RS + ch * 4]), Kg + row * Dd + ch * 4);
    }
    CPA_COMMIT();
    CPA_WAIT(0);
    __syncthreads();
    // split Q: 64 rows x 32 d-pairs
#pragma unroll
    for (int i = 0; i < 8; i++) {
        int p = tid + i * NT;
        int row = p >> 5, j = p & 31;
        float2 x = *(float2*)&VRAW[row * RS + 2 * j];
        unsigned h, l;
        split_pair(x.x, x.y, h, l);
        QH[row * BSW + j] = h;
        QL[row * BSW + j] = l;
    }
    __syncthreads();

    float l0 = 0.0f, l1 = 0.0f;
    float cacc[4][4];
#pragma unroll
    for (int n = 0; n < 4; n++)
#pragma unroll
        for (int j = 0; j < 4; j++) cacc[n][j] = 0.0f;

    // ================= Fused sweep over K tiles =================
    for (int kt = 0; kt < KTILES; kt++) {
        // Issue V(kt) raw copy (overlaps everything up to V-split)
        {
            const float* src = Vg + (size_t)kt * TK * Dd;
#pragma unroll
            for (int i = 0; i < 4; i++) {
                int c = tid + i * NT;
                int row = c >> 4, ch = c & 15;
                cpa16(smem_u32(&VRAW[row * RS + ch * 4]), src + row * Dd + ch * 4);
            }
            CPA_COMMIT();
        }
        CPA_WAIT(1);        // K(kt) raw complete (V(kt) may be pending)
        __syncthreads();

        // ---- split K(kt): KRAW -> KH/KL ----
#pragma unroll
        for (int i = 0; i < 8; i++) {
            int p = tid + i * NT;
            int row = p >> 5, j = p & 31;
            float2 x = *(float2*)&KRAW[row * RS + 2 * j];
            unsigned h, l;
            split_pair(x.x, x.y, h, l);
            KH[row * BSW + j] = h;
            KL[row * BSW + j] = l;
        }
        __syncthreads();

        // Prefetch mask words
        const unsigned w0 = mb_r0[kt * 2 + wcol];
        const unsigned w1 = mb_r1[kt * 2 + wcol];

        // ---- S = Q K^T on this warp's 16x32 patch (bf16 3-pass) ----
        float sacc[4][4];
#pragma unroll
        for (int n = 0; n < 4; n++)
#pragma unroll
            for (int j = 0; j < 4; j++) sacc[n][j] = 0.0f;

#pragma unroll
        for (int ksi = 0; ksi < 4; ksi++) {
            const int kw = ksi * 8 + tig;      // word index of k-pair
            unsigned ah0 = QH[r0 * BSW + kw];
            unsigned ah1 = QH[r1 * BSW + kw];
            unsigned ah2 = QH[r0 * BSW + kw + 4];
            unsigned ah3 = QH[r1 * BSW + kw + 4];
            unsigned al0 = QL[r0 * BSW + kw];
            unsigned al1 = QL[r1 * BSW + kw];
            unsigned al2 = QL[r0 * BSW + kw + 4];
            unsigned al3 = QL[r1 * BSW + kw + 4];
            unsigned bh0[4], bh1[4], bl0[4], bl1[4];
#pragma unroll
            for (int j = 0; j < 4; j++) {
                const int col = cb + j * 8 + gid;
                bh0[j] = KH[col * BSW + kw];
                bh1[j] = KH[col * BSW + kw + 4];
                bl0[j] = KL[col * BSW + kw];
                bl1[j] = KL[col * BSW + kw + 4];
            }
#pragma unroll
            for (int j = 0; j < 4; j++)
                mma16(sacc[j], ah0, ah1, ah2, ah3, bh0[j], bh1[j]);
#pragma unroll
            for (int j = 0; j < 4; j++)
                mma16(sacc[j], al0, al1, al2, al3, bh0[j], bh1[j]);
#pragma unroll
            for (int j = 0; j < 4; j++)
                mma16(sacc[j], ah0, ah1, ah2, ah3, bl0[j], bl1[j]);
        }

        // ---- Epilogue: e = mask ? 0 : exp(s*scale); att + P(split) + l ----
#pragma unroll
        for (int nb = 0; nb < 4; nb++) {
            const int ct = nb * 8 + 2 * tig;
            float e00 = ((w0 >> ct) & 1u)       ? 0.0f : __expf(sacc[nb][0] * scale);
            float e01 = ((w0 >> (ct + 1)) & 1u) ? 0.0f : __expf(sacc[nb][1] * scale);
            float e10 = ((w1 >> ct) & 1u)       ? 0.0f : __expf(sacc[nb][2] * scale);
            float e11 = ((w1 >> (ct + 1)) & 1u) ? 0.0f : __expf(sacc[nb][3] * scale);

            const int col = kt * TK + cb + ct;
            *(float2*)(att + (size_t)r0 * Ss + col) = make_float2(e00, e01);
            *(float2*)(att + (size_t)r1 * Ss + col) = make_float2(e10, e11);

            unsigned h, l;
            const int pw = (cb >> 1) + nb * 4 + tig;
            split_pair(e00, e01, h, l);
            PH[r0 * BSW + pw] = h;  PL[r0 * BSW + pw] = l;
            split_pair(e10, e11, h, l);
            PH[r1 * BSW + pw] = h;  PL[r1 * BSW + pw] = l;

            l0 += e00 + e01;
            l1 += e10 + e11;
        }
        __syncthreads();    // P ready; KRAW/KH/KL free

        // Issue K(kt+1) raw copy (overlaps V-split + PV)
        if (kt + 1 < KTILES) {
            const float* src = Kg + (size_t)(kt + 1) * TK * Dd;
#pragma unroll
            for (int i = 0; i < 4; i++) {
                int c = tid + i * NT;
                int row = c >> 4, ch = c & 15;
                cpa16(smem_u32(&KRAW[row * RS + ch * 4]), src + row * Dd + ch * 4);
            }
            CPA_COMMIT();
            CPA_WAIT(1);    // V(kt) raw complete
        } else {
            CPA_WAIT(0);
        }
        __syncthreads();    // V raw visible to all threads

        // ---- split+transpose V(kt): VRAW[k][d] -> VTH/VTL[n][k-pairs] ----
#pragma unroll
        for (int i = 0; i < 8; i++) {
            int p = tid + i * NT;
            int n = p & 63, kp = p >> 6;
            float x0 = VRAW[(2 * kp) * RS + n];
            float x1 = VRAW[(2 * kp + 1) * RS + n];
            unsigned h, l;
            split_pair(x0, x1, h, l);
            VTH[n * BSW + kp] = h;
            VTL[n * BSW + kp] = l;
        }
        __syncthreads();    // VT ready

        // ---- O += P V (bf16 3-pass) ----
#pragma unroll
        for (int ksi = 0; ksi < 4; ksi++) {
            const int kw = ksi * 8 + tig;
            unsigned ah0 = PH[r0 * BSW + kw];
            unsigned ah1 = PH[r1 * BSW + kw];
            unsigned ah2 = PH[r0 * BSW + kw + 4];
            unsigned ah3 = PH[r1 * BSW + kw + 4];
            unsigned al0 = PL[r0 * BSW + kw];
            unsigned al1 = PL[r1 * BSW + kw];
            unsigned al2 = PL[r0 * BSW + kw + 4];
            unsigned al3 = PL[r1 * BSW + kw + 4];
            unsigned bh0[4], bh1[4], bl0[4], bl1[4];
#pragma unroll
            for (int j = 0; j < 4; j++) {
                const int n = cb + j * 8 + gid;
                bh0[j] = VTH[n * BSW + kw];
                bh1[j] = VTH[n * BSW + kw + 4];
                bl0[j] = VTL[n * BSW + kw];
                bl1[j] = VTL[n * BSW + kw + 4];
            }
#pragma unroll
            for (int j = 0; j < 4; j++)
                mma16(cacc[j], ah0, ah1, ah2, ah3, bh0[j], bh1[j]);
#pragma unroll
            for (int j = 0; j < 4; j++)
                mma16(cacc[j], al0, al1, al2, al3, bh0[j], bh1[j]);
#pragma unroll
            for (int j = 0; j < 4; j++)
                mma16(cacc[j], ah0, ah1, ah2, ah3, bl0[j], bl1[j]);
        }
        __syncthreads();    // VT/P/VRAW free for next iteration
    }

    // ---- Finalize l: quad reduce, then combine the two col-halves ----
#pragma unroll
    for (int off = 1; off <= 2; off <<= 1) {
        l0 += __shfl_xor_sync(0xffffffffu, l0, off);
        l1 += __shfl_xor_sync(0xffffffffu, l1, off);
    }
    float* red = KRAW;   // all cp.async drained; post-barrier reuse
    if (tig == 0) {
        red[r0 * 2 + wcol] = l0;
        red[r1 * 2 + wcol] = l1;
    }
    __syncthreads();
    const float inv0 = 1.0f / (red[r0 * 2] + red[r0 * 2 + 1]);
    const float inv1 = 1.0f / (red[r1 * 2] + red[r1 * 2 + 1]);
    if (wcol == 0 && tig == 0) {
        g_invl[(size_t)bh * Ss + q0 + r0] = inv0;
        g_invl[(size_t)bh * Ss + q0 + r1] = inv1;
    }

    // ---- Write context = O / l ----
#pragma unroll
    for (int nb = 0; nb < 4; nb++) {
        const int col = cb + nb * 8 + 2 * tig;
        *(float2*)(ctx + (size_t)r0 * Dd + col) =
            make_float2(cacc[nb][0] * inv0, cacc[nb][1] * inv0);
        *(float2*)(ctx + (size_t)r1 * Dd + col) =
            make_float2(cacc[nb][2] * inv1, cacc[nb][3] * inv1);
    }
}

// Streaming normalize: att[row][k] *= 1/l[row]
__global__ void att_norm_kernel(float4* __restrict__ att4)
{
    const size_t total4 = (size_t)Bb * Hh * Ss * Ss / 4;   // 33554432
    size_t i = (size_t)blockIdx.x * blockDim.x + threadIdx.x;
    const size_t stride = (size_t)gridDim.x * blockDim.x;
    for (size_t j = i; j < total4; j += stride) {
        const float inv = g_invl[j >> 9];      // 512 float4 per row
        float4 v = att4[j];
        v.x *= inv; v.y *= inv; v.z *= inv; v.w *= inv;
        att4[j] = v;
    }
}

extern "C" void kernel_launch(void* const* d_in, const int* in_sizes, int n_in,
                              void* d_out, int out_size)
{
    const float* Q = (const float*)d_in[0];
    const float* K = (const float*)d_in[1];
    const float* V = (const float*)d_in[2];
    const void*  M = d_in[3];
    // d_in[4] = dim_key (constant 64), unused

    float* out = (float*)d_out;
    float* ctx = out;                                   // [B,H,S,D]
    float* att = out + (size_t)Bb * Hh * Ss * Dd;       // [B,H,S,S]

    const size_t smem = SMEM_FLOATS * sizeof(float);    // 108544 B
    cudaFuncSetAttribute(attn_mma_kernel,
                         cudaFuncAttributeMaxDynamicSharedMemorySize, (int)smem);

    detect_mask_kernel<<<1, NT>>>((const unsigned int*)M);
    mask_pack_kernel<<<(MASK_WORDS + NT - 1) / NT, NT>>>(M);

    dim3 grid(Ss / TQ, Bb * Hh);                        // (32, 32) = 1024 CTAs
    attn_mma_kernel<<<grid, NT, smem>>>(Q, K, V, ctx, att);

    att_norm_kernel<<<2048, 256>>>((float4*)att);
}

// round 16
// speedup vs baseline: 3.7755x; 1.0886x over previous
#include <cuda_runtime.h>
#include <math_constants.h>

// Problem constants
#define Bb 2
#define Hh 16
#define Ss 2048
#define Dd 64

// Tiling: CTA = 64 q-rows, 8 warps, warp tile 16 rows x 32 cols
#define TQ 64
#define TK 64
#define NT 256
#define KTILES (Ss / TK)        // 32
#define TILE_F (TK * Dd)        // 4096 floats per K/V tile

// bf16 arrays: row stride 36 words (=72 bf16): fragment lane bank = 4*gid+tig
#define BSW 36

// smem layout in 32-bit words
#define OFF_QH   0              // each buffer 64*36 = 2304 words
#define OFF_QL   2304
#define OFF_KH   4608
#define OFF_KL   6912
#define OFF_VTH  9216
#define OFF_VTL  11520
#define OFF_PH   13824
#define OFF_PL   16128
#define SMEM_WORDS 18432        // 73728 B

// mask dtype flag: 1 -> 4-byte elements, 0 -> 1-byte
__device__ int g_mask_elem4;
// packed mask bits: [B, S, S/32]
#define MASK_WORDS (Bb * Ss * (Ss / 32))
__device__ unsigned g_maskbits[MASK_WORDS];
// per-row 1/l for the normalize pass: [B*H*S]
__device__ float g_invl[Bb * Hh * Ss];

__global__ void detect_mask_kernel(const unsigned int* __restrict__ mw)
{
    int has_bigbyte = 0, has_bigword = 0;
    for (int i = threadIdx.x; i < 4096; i += NT) {
        unsigned w = mw[i];
        if ((w & 0xffu) > 1u || ((w >> 8) & 0xffu) > 1u ||
            ((w >> 16) & 0xffu) > 1u || ((w >> 24) & 0xffu) > 1u) has_bigbyte = 1;
        if (w > 1u) has_bigword = 1;
    }
    has_bigbyte = __syncthreads_or(has_bigbyte);
    has_bigword = __syncthreads_or(has_bigword);
    if (threadIdx.x == 0)
        g_mask_elem4 = has_bigbyte ? 1 : (has_bigword ? 0 : 1);
}

__global__ void mask_pack_kernel(const void* __restrict__ mask)
{
    int w = blockIdx.x * blockDim.x + threadIdx.x;
    if (w >= MASK_WORDS) return;
    unsigned bits = 0;
    if (g_mask_elem4) {
        const uint4* p = (const uint4*)mask + (size_t)w * 8;
#pragma unroll
        for (int j = 0; j < 8; j++) {
            uint4 v = p[j];
            bits |= ((unsigned)(v.x != 0u)) << (4 * j);
            bits |= ((unsigned)(v.y != 0u)) << (4 * j + 1);
            bits |= ((unsigned)(v.z != 0u)) << (4 * j + 2);
            bits |= ((unsigned)(v.w != 0u)) << (4 * j + 3);
        }
    } else {
        const uint4* p = (const uint4*)mask + (size_t)w * 2;
#pragma unroll
        for (int j = 0; j < 2; j++) {
            uint4 v = p[j];
            unsigned vv[4] = {v.x, v.y, v.z, v.w};
#pragma unroll
            for (int q = 0; q < 4; q++)
#pragma unroll
                for (int bbit = 0; bbit < 4; bbit++)
                    bits |= ((unsigned)(((vv[q] >> (8 * bbit)) & 0xffu) != 0u))
                            << (16 * j + 4 * q + bbit);
        }
    }
    g_maskbits[w] = bits;
}

// pack two f32 into bf16x2: x0 -> low half, x1 -> high half (globally consistent)
__device__ __forceinline__ unsigned pack2(float x0, float x1)
{
    unsigned r;
    asm("cvt.rn.bf16x2.f32 %0, %1, %2;" : "=r"(r) : "f"(x1), "f"(x0));
    return r;
}

// split a pair into packed hi & lo bf16x2
__device__ __forceinline__ void split_pair(float x0, float x1,
                                           unsigned& hi, unsigned& lo)
{
    hi = pack2(x0, x1);
    float h0 = __uint_as_float(hi << 16);
    float h1 = __uint_as_float(hi & 0xffff0000u);
    lo = pack2(x0 - h0, x1 - h1);
}

__device__ __forceinline__ void mma16(float* c,
                                      unsigned a0, unsigned a1, unsigned a2, unsigned a3,
                                      unsigned b0, unsigned b1)
{
    asm volatile(
        "mma.sync.aligned.m16n8k16.row.col.f32.bf16.bf16.f32 "
        "{%0,%1,%2,%3}, {%4,%5,%6,%7}, {%8,%9}, {%0,%1,%2,%3};\n"
        : "+f"(c[0]), "+f"(c[1]), "+f"(c[2]), "+f"(c[3])
        : "r"(a0), "r"(a1), "r"(a2), "r"(a3), "r"(b0), "r"(b1));
}

__global__ __launch_bounds__(NT, 2)
void attn_mma_kernel(const float* __restrict__ Qg_,
                     const float* __restrict__ Kg_,
                     const float* __restrict__ Vg_,
                     float* __restrict__ ctx_out,
                     float* __restrict__ att_out)
{
    extern __shared__ unsigned smw[];
    const int tid  = threadIdx.x;
    const int lane = tid & 31;
    const int wid  = tid >> 5;          // 8 warps
    const int gid  = lane >> 2;         // 0..7
    const int tig  = lane & 3;          // 0..3
    const int wrow = wid >> 1;          // 0..3
    const int wcol = wid & 1;           // 0..1
    const int cb   = wcol * 32;         // col base within 64-wide tile
    const int r0   = wrow * 16 + gid;
    const int r1   = r0 + 8;

    const int qt = blockIdx.x;
    const int bh = blockIdx.y;
    const int b  = bh >> 4;
    const int q0 = qt * TQ;

    const size_t head_off = (size_t)bh * Ss * Dd;
    const float* Qg = Qg_ + head_off + (size_t)q0 * Dd;
    const float* Kg = Kg_ + head_off;
    const float* Vg = Vg_ + head_off;
    float* att = att_out + (size_t)bh * Ss * Ss + (size_t)q0 * Ss;
    float* ctx = ctx_out + head_off + (size_t)q0 * Dd;
    const unsigned* mb_r0 = g_maskbits + ((size_t)b * Ss + q0 + r0) * (Ss / 32);
    const unsigned* mb_r1 = g_maskbits + ((size_t)b * Ss + q0 + r1) * (Ss / 32);

    const float scale = 0.125f;     // 1/sqrt(64)

    unsigned* QH  = smw + OFF_QH;
    unsigned* QL  = smw + OFF_QL;
    unsigned* KH  = smw + OFF_KH;
    unsigned* KL  = smw + OFF_KL;
    unsigned* VTH = smw + OFF_VTH;
    unsigned* VTL = smw + OFF_VTL;
    unsigned* PH  = smw + OFF_PH;
    unsigned* PL  = smw + OFF_PL;

    // Per-thread staging coordinates:
    //  K/Q: rows wid+8i (i=0..7), float2 at col-pair j = lane
    //  V:   k-pair kp = (wid>>1)+4i (i=0..7), col n = (wid&1)*32 + lane
    const int vn = (wid & 1) * 32 + lane;

    // ---- Prologue: LDG Q, split->smem; LDG K(0), V(0) into registers ----
    {
        float2 qreg;
#pragma unroll
        for (int i = 0; i < 8; i++) {
            const int row = wid + 8 * i;
            qreg = *(const float2*)&Qg[row * Dd + 2 * lane];
            unsigned h, l;
            split_pair(qreg.x, qreg.y, h, l);
            QH[row * BSW + lane] = h;
            QL[row * BSW + lane] = l;
        }
    }
    float2 kreg[8], vreg[8];
#pragma unroll
    for (int i = 0; i < 8; i++)
        kreg[i] = *(const float2*)&Kg[(wid + 8 * i) * Dd + 2 * lane];
#pragma unroll
    for (int i = 0; i < 8; i++) {
        const int kp = (wid >> 1) + 4 * i;
        vreg[i].x = Vg[(2 * kp) * Dd + vn];
        vreg[i].y = Vg[(2 * kp + 1) * Dd + vn];
    }

    float l0 = 0.0f, l1 = 0.0f;
    float cacc[4][4];
#pragma unroll
    for (int n = 0; n < 4; n++)
#pragma unroll
        for (int j = 0; j < 4; j++) cacc[n][j] = 0.0f;

    // ================= Fused sweep, 2 barriers per tile =================
    for (int kt = 0; kt < KTILES; kt++) {
        // ---- split K(kt) regs -> KH/KL; then prefetch K(kt+1) ----
#pragma unroll
        for (int i = 0; i < 8; i++) {
            const int row = wid + 8 * i;
            unsigned h, l;
            split_pair(kreg[i].x, kreg[i].y, h, l);
            KH[row * BSW + lane] = h;
            KL[row * BSW + lane] = l;
        }
        if (kt + 1 < KTILES) {
            const float* src = Kg + (size_t)(kt + 1) * TILE_F;
#pragma unroll
            for (int i = 0; i < 8; i++)
                kreg[i] = *(const float2*)&src[(wid + 8 * i) * Dd + 2 * lane];
        }
        __syncthreads();    // [B1] K (and Q) visible; prev PV reads retired

        const unsigned w0 = mb_r0[kt * 2 + wcol];
        const unsigned w1 = mb_r1[kt * 2 + wcol];

        // ---- S = Q K^T on this warp's 16x32 patch (bf16 3-pass) ----
        float sacc[4][4];
#pragma unroll
        for (int n = 0; n < 4; n++)
#pragma unroll
            for (int j = 0; j < 4; j++) sacc[n][j] = 0.0f;

#pragma unroll
        for (int ksi = 0; ksi < 4; ksi++) {
            const int kw = ksi * 8 + tig;
            unsigned ah0 = QH[r0 * BSW + kw];
            unsigned ah1 = QH[r1 * BSW + kw];
            unsigned ah2 = QH[r0 * BSW + kw + 4];
            unsigned ah3 = QH[r1 * BSW + kw + 4];
            unsigned al0 = QL[r0 * BSW + kw];
            unsigned al1 = QL[r1 * BSW + kw];
            unsigned al2 = QL[r0 * BSW + kw + 4];
            unsigned al3 = QL[r1 * BSW + kw + 4];
            unsigned bh0[4], bh1[4], bl0[4], bl1[4];
#pragma unroll
            for (int j = 0; j < 4; j++) {
                const int col = cb + j * 8 + gid;
                bh0[j] = KH[col * BSW + kw];
                bh1[j] = KH[col * BSW + kw + 4];
                bl0[j] = KL[col * BSW + kw];
                bl1[j] = KL[col * BSW + kw + 4];
            }
#pragma unroll
            for (int j = 0; j < 4; j++)
                mma16(sacc[j], ah0, ah1, ah2, ah3, bh0[j], bh1[j]);
#pragma unroll
            for (int j = 0; j < 4; j++)
                mma16(sacc[j], al0, al1, al2, al3, bh0[j], bh1[j]);
#pragma unroll
            for (int j = 0; j < 4; j++)
                mma16(sacc[j], ah0, ah1, ah2, ah3, bl0[j], bl1[j]);
        }

        // ---- Epilogue: e = mask ? 0 : exp(s*scale); att + P(split) + l ----
#pragma unroll
        for (int nb = 0; nb < 4; nb++) {
            const int ct = nb * 8 + 2 * tig;
            float e00 = ((w0 >> ct) & 1u)       ? 0.0f : __expf(sacc[nb][0] * scale);
            float e01 = ((w0 >> (ct + 1)) & 1u) ? 0.0f : __expf(sacc[nb][1] * scale);
            float e10 = ((w1 >> ct) & 1u)       ? 0.0f : __expf(sacc[nb][2] * scale);
            float e11 = ((w1 >> (ct + 1)) & 1u) ? 0.0f : __expf(sacc[nb][3] * scale);

            const int col = kt * TK + cb + ct;
            *(float2*)(att + (size_t)r0 * Ss + col) = make_float2(e00, e01);
            *(float2*)(att + (size_t)r1 * Ss + col) = make_float2(e10, e11);

            unsigned h, l;
            const int pw = (cb >> 1) + nb * 4 + tig;
            split_pair(e00, e01, h, l);
            PH[r0 * BSW + pw] = h;  PL[r0 * BSW + pw] = l;
            split_pair(e10, e11, h, l);
            PH[r1 * BSW + pw] = h;  PL[r1 * BSW + pw] = l;

            l0 += e00 + e01;
            l1 += e10 + e11;
        }

        // ---- split+transpose V(kt) regs -> VTH/VTL; prefetch V(kt+1) ----
#pragma unroll
        for (int i = 0; i < 8; i++) {
            const int kp = (wid >> 1) + 4 * i;
            unsigned h, l;
            split_pair(vreg[i].x, vreg[i].y, h, l);
            VTH[vn * BSW + kp] = h;
            VTL[vn * BSW + kp] = l;
        }
        if (kt + 1 < KTILES) {
            const float* src = Vg + (size_t)(kt + 1) * TILE_F;
#pragma unroll
            for (int i = 0; i < 8; i++) {
                const int kp = (wid >> 1) + 4 * i;
                vreg[i].x = src[(2 * kp) * Dd + vn];
                vreg[i].y = src[(2 * kp + 1) * Dd + vn];
            }
        }
        __syncthreads();    // [B2] P + VT visible; QK reads of KH/KL retired

        // ---- O += P V (bf16 3-pass) ----
#pragma unroll
        for (int ksi = 0; ksi < 4; ksi++) {
            const int kw = ksi * 8 + tig;
            unsigned ah0 = PH[r0 * BSW + kw];
            unsigned ah1 = PH[r1 * BSW + kw];
            unsigned ah2 = PH[r0 * BSW + kw + 4];
            unsigned ah3 = PH[r1 * BSW + kw + 4];
            unsigned al0 = PL[r0 * BSW + kw];
            unsigned al1 = PL[r1 * BSW + kw];
            unsigned al2 = PL[r0 * BSW + kw + 4];
            unsigned al3 = PL[r1 * BSW + kw + 4];
            unsigned bh0[4], bh1[4], bl0[4], bl1[4];
#pragma unroll
            for (int j = 0; j < 4; j++) {
                const int n = cb + j * 8 + gid;
                bh0[j] = VTH[n * BSW + kw];
                bh1[j] = VTH[n * BSW + kw + 4];
                bl0[j] = VTL[n * BSW + kw];
                bl1[j] = VTL[n * BSW + kw + 4];
            }
#pragma unroll
            for (int j = 0; j < 4; j++)
                mma16(cacc[j], ah0, ah1, ah2, ah3, bh0[j], bh1[j]);
#pragma unroll
            for (int j = 0; j < 4; j++)
                mma16(cacc[j], al0, al1, al2, al3, bh0[j], bh1[j]);
#pragma unroll
            for (int j = 0; j < 4; j++)
                mma16(cacc[j], ah0, ah1, ah2, ah3, bl0[j], bl1[j]);
        }
        // no barrier: next iter's [B1] orders PV reads vs next VT/P writes
    }

    // ---- Finalize l: quad reduce, combine col-halves via smem ----
#pragma unroll
    for (int off = 1; off <= 2; off <<= 1) {
        l0 += __shfl_xor_sync(0xffffffffu, l0, off);
        l1 += __shfl_xor_sync(0xffffffffu, l1, off);
    }
    __syncthreads();                    // all PV reads done; smem reusable
    float* red = (float*)smw;
    if (tig == 0) {
        red[r0 * 2 + wcol] = l0;
        red[r1 * 2 + wcol] = l1;
    }
    __syncthreads();
    const float inv0 = 1.0f / (red[r0 * 2] + red[r0 * 2 + 1]);
    const float inv1 = 1.0f / (red[r1 * 2] + red[r1 * 2 + 1]);
    if (wcol == 0 && tig == 0) {
        g_invl[(size_t)bh * Ss + q0 + r0] = inv0;
        g_invl[(size_t)bh * Ss + q0 + r1] = inv1;
    }

    // ---- Write context = O / l ----
#pragma unroll
    for (int nb = 0; nb < 4; nb++) {
        const int col = cb + nb * 8 + 2 * tig;
        *(float2*)(ctx + (size_t)r0 * Dd + col) =
            make_float2(cacc[nb][0] * inv0, cacc[nb][1] * inv0);
        *(float2*)(ctx + (size_t)r1 * Dd + col) =
            make_float2(cacc[nb][2] * inv1, cacc[nb][3] * inv1);
    }
}

// Streaming normalize: att[row][k] *= 1/l[row]
__global__ void att_norm_kernel(float4* __restrict__ att4)
{
    const size_t total4 = (size_t)Bb * Hh * Ss * Ss / 4;   // 33554432
    size_t i = (size_t)blockIdx.x * blockDim.x + threadIdx.x;
    const size_t stride = (size_t)gridDim.x * blockDim.x;
    for (size_t j = i; j < total4; j += stride) {
        const float inv = g_invl[j >> 9];      // 512 float4 per row
        float4 v = att4[j];
        v.x *= inv; v.y *= inv; v.z *= inv; v.w *= inv;
        att4[j] = v;
    }
}

extern "C" void kernel_launch(void* const* d_in, const int* in_sizes, int n_in,
                              void* d_out, int out_size)
{
    const float* Q = (const float*)d_in[0];
    const float* K = (const float*)d_in[1];
    const float* V = (const float*)d_in[2];
    const void*  M = d_in[3];
    // d_in[4] = dim_key (constant 64), unused

    float* out = (float*)d_out;
    float* ctx = out;                                   // [B,H,S,D]
    float* att = out + (size_t)Bb * Hh * Ss * Dd;       // [B,H,S,S]

    const size_t smem = SMEM_WORDS * sizeof(unsigned);  // 73728 B
    cudaFuncSetAttribute(attn_mma_kernel,
                         cudaFuncAttributeMaxDynamicSharedMemorySize, (int)smem);

    detect_mask_kernel<<<1, NT>>>((const unsigned int*)M);
    mask_pack_kernel<<<(MASK_WORDS + NT - 1) / NT, NT>>>(M);

    dim3 grid(Ss / TQ, Bb * Hh);                        // (32, 32) = 1024 CTAs
    attn_mma_kernel<<<grid, NT, smem>>>(Q, K, V, ctx, att);

    att_norm_kernel<<<2048, 256>>>((float4*)att);
}